// round 13
// baseline (speedup 1.0000x reference)
#include <cuda_runtime.h>
#include <cuda_fp16.h>
#include <math.h>
#include <stdint.h>

#define BATCH 768
#define NS 32
#define NP 24
#define EDIM 64
#define HDIM 128
#define G4 512      // 4*HDIM
#define P1D 512     // pool hidden
#define BNK 1024
#define MLPD 1024
#define KTOT (HDIM + BNK)   // 1152
#define TSTEPS 12
#define NCTA 144
#define NT 512      // threads per CTA

// ---------------- scratch (static device memory; no allocations) ----------------
__device__ float g_pos[BATCH * 2];
__device__ float g_decin[BATCH * EDIM];
__device__ float g_h[BATCH * HDIM];
__device__ float g_c[BATCH * HDIM];
__device__ float g_hmid[BATCH * HDIM];
__device__ float g_hterm[BATCH * P1D];
__device__ float g_pool[(size_t)BATCH * BNK];
__device__ float g_dh[(size_t)BATCH * MLPD];
__device__ float g_M2[2 * P1D];
__device__ float g_cb[P1D];
__device__ __half g_Wp2t[(size_t)BNK * P1D];       // W_p2^T fp16
__device__ __half g_Wm1t[(size_t)MLPD * KTOT];     // W_m1^T fp16
__device__ float g_Wm2t[HDIM * MLPD];              // W_m2^T
__device__ float g_Wiht[G4 * EDIM];                // W_ih^T
__device__ float g_Whht[G4 * HDIM];                // W_hh^T
__device__ float g_Wp1t[P1D * HDIM];               // W_p1[64:192]^T
__device__ unsigned g_bar_cnt[256];
__device__ unsigned g_bar_sense;

__device__ __forceinline__ float sigf(float x) { return 1.f / (1.f + expf(-x)); }

__device__ __forceinline__ void mma_f16(float* d, const uint32_t* a, const uint32_t* b) {
    asm volatile(
        "mma.sync.aligned.m16n8k16.row.col.f32.f16.f16.f32 "
        "{%0,%1,%2,%3}, {%4,%5,%6,%7}, {%8,%9}, {%0,%1,%2,%3};"
        : "+f"(d[0]), "+f"(d[1]), "+f"(d[2]), "+f"(d[3])
        : "r"(a[0]), "r"(a[1]), "r"(a[2]), "r"(a[3]), "r"(b[0]), "r"(b[1]));
}

__device__ __forceinline__ void ldsm_x4(uint32_t* r, uint32_t saddr) {
    asm volatile("ldmatrix.sync.aligned.m8n8.x4.shared.b16 {%0,%1,%2,%3}, [%4];"
                 : "=r"(r[0]), "=r"(r[1]), "=r"(r[2]), "=r"(r[3]) : "r"(saddr));
}

__device__ __forceinline__ uint32_t smem_u32(const void* p) {
    uint32_t a;
    asm("{ .reg .u64 t; cvta.to.shared.u64 t, %1; cvt.u32.u64 %0, t; }" : "=r"(a) : "l"(p));
    return a;
}
__device__ __forceinline__ void cp_async16(uint32_t saddr, const void* g) {
    asm volatile("cp.async.cg.shared.global [%0], [%1], 16;" :: "r"(saddr), "l"(g));
}
#define CP_COMMIT() asm volatile("cp.async.commit_group;" ::: "memory")
#define CP_WAIT(n)  asm volatile("cp.async.wait_group %0;" :: "n"(n) : "memory")

// ---- two-level tree barrier (12 groups of 12; monotonic counters, replay-safe) ----
__device__ __forceinline__ void grid_bar(unsigned target) {
    __syncthreads();
    if (threadIdx.x == 0) {
        __threadfence();
        int g = blockIdx.x / 12;
        unsigned old = atomicAdd(&g_bar_cnt[g * 16], 1u);
        bool released = false;
        if ((old + 1u) % 12u == 0u) {
            unsigned o2 = atomicAdd(&g_bar_cnt[12 * 16], 1u);
            if ((o2 + 1u) % 12u == 0u) {
                __threadfence();
                atomicAdd(&g_bar_sense, 1u);
                released = true;
            }
        }
        if (!released) {
            while ((int)(*(volatile unsigned*)&g_bar_sense - target) < 0)
                __nanosleep(32);
        }
        __threadfence();
    }
    __syncthreads();
}

// ---------------- setup ----------------
__global__ void setup_kernel(const float* __restrict__ last_pos,
                             const float* __restrict__ last_pos_rel,
                             const float* __restrict__ h0, const float* __restrict__ c0,
                             const float* __restrict__ W_se, const float* __restrict__ b_se,
                             const float* __restrict__ W_pse, const float* __restrict__ b_pse,
                             const float* __restrict__ W_p1, const float* __restrict__ b_p1,
                             const float* __restrict__ W_p2, const float* __restrict__ W_m1,
                             const float* __restrict__ W_m2,
                             const float* __restrict__ W_ih, const float* __restrict__ W_hh) {
    int tid = blockIdx.x * blockDim.x + threadIdx.x;
    int nt = gridDim.x * blockDim.x;
    for (int i = tid; i < BATCH * 2; i += nt) g_pos[i] = last_pos[i];
    for (int i = tid; i < BATCH * HDIM; i += nt) { g_h[i] = h0[i]; g_c[i] = c0[i]; }
    for (int i = tid; i < BATCH * EDIM; i += nt) {
        int b = i >> 6, e = i & 63;
        g_decin[i] = b_se[e] + last_pos_rel[b * 2] * W_se[e] + last_pos_rel[b * 2 + 1] * W_se[EDIM + e];
    }
    for (int i = tid; i < 2 * P1D; i += nt) {
        int d = i >> 9, t = i & 511;
        float a = 0.f;
        for (int e = 0; e < EDIM; e++) a += W_pse[d * EDIM + e] * W_p1[e * P1D + t];
        g_M2[i] = a;
    }
    for (int i = tid; i < P1D; i += nt) {
        float a = b_p1[i];
        for (int e = 0; e < EDIM; e++) a += b_pse[e] * W_p1[e * P1D + i];
        g_cb[i] = a;
    }
    for (int i = tid; i < BNK * P1D; i += nt) {
        int n = i / P1D, k = i % P1D;
        g_Wp2t[i] = __float2half_rn(W_p2[(size_t)k * BNK + n]);
    }
    for (int i = tid; i < MLPD * KTOT; i += nt) {
        int n = i / KTOT, k = i % KTOT;
        g_Wm1t[i] = __float2half_rn(W_m1[(size_t)k * MLPD + n]);
    }
    for (int i = tid; i < HDIM * MLPD; i += nt) {
        int n = i / MLPD, k = i % MLPD;
        g_Wm2t[i] = W_m2[(size_t)k * HDIM + n];
    }
    for (int i = tid; i < G4 * EDIM; i += nt) {
        int g = i / EDIM, k = i % EDIM;
        g_Wiht[i] = W_ih[(size_t)k * G4 + g];
    }
    for (int i = tid; i < G4 * HDIM; i += nt) {
        int g = i / HDIM, k = i % HDIM;
        g_Whht[i] = W_hh[(size_t)k * G4 + g];
    }
    for (int i = tid; i < P1D * HDIM; i += nt) {
        int n = i / HDIM, k = i % HDIM;
        g_Wp1t[i] = W_p1[(size_t)(EDIM + k) * P1D + n];
    }
}

// ---------------- persistent all-steps kernel (512 threads) ----------------
#define SMB_A 0
#define SMB_B 131072
#define SMB_D 163840
#define SMEM_GP (163840 + 128 * 136 * 2)   // 198656
#define DP 136
#define GP_KC 64
#define KP 72

__global__ __launch_bounds__(NT) void decoder_persistent(
    const float* __restrict__ b_ih, const float* __restrict__ b_hh,
    const float* __restrict__ W_hp, const float* __restrict__ b_hp,
    const float* __restrict__ W_se, const float* __restrict__ b_se,
    const float* __restrict__ bp2, const float* __restrict__ bm1,
    const float* __restrict__ bm2,
    float* __restrict__ out) {
    extern __shared__ char smraw[];
    const int tid = threadIdx.x;
    const int bx = blockIdx.x;
    const int wid = tid >> 5, lane = tid & 31;
    const int gid = lane >> 2, tig = lane & 3;
    const int q = lane >> 3;
    const int mrow = (q & 1) * 8 + (lane & 7);
    const int mkof = (q >> 1) * 8;
    const uint32_t swz = (uint32_t)(lane & 7) << 4;
    const uint32_t sb = smem_u32(smraw);

    unsigned base = *(volatile unsigned*)&g_bar_sense;
    unsigned bc = 0;

    for (int t = 0; t < TSTEPS; t++) {
        // ===== phase A: [mlp2 of prev dh ->] h, LSTM, hidden2pos, pos, dec_in, hterm ====
        if (bx < 128) {
            const int row0 = bx * 6;
            float* s_dh = (float*)smraw;             // 6*1024
            float* s_h = s_dh + 6 * MLPD;            // 6*128
            float* s_x = s_h + 6 * HDIM;             // 6*64
            float* s_g = s_x + 6 * EDIM;             // 6*512
            float* s_rel = s_g + 6 * G4;             // 12
            {
                float4 z = make_float4(0.f, 0.f, 0.f, 0.f);
                float4* pz = (float4*)(g_pool + (size_t)row0 * BNK);
                for (int i = tid; i < 6 * BNK / 4; i += NT) pz[i] = z;
            }
            if (t == 0) {
                for (int i = tid; i < 6 * HDIM; i += NT) s_h[i] = g_h[row0 * HDIM + i];
            } else {
                const float4* src = (const float4*)(g_dh + (size_t)row0 * MLPD);
                float4* dst = (float4*)s_dh;
                for (int i = tid; i < 6 * MLPD / 4; i += NT) dst[i] = src[i];
                __syncthreads();
                for (int i = tid; i < 6 * HDIM; i += NT) {
                    int row = i >> 7, n = i & 127;
                    float a0 = bm2[n];
                    const float4* wt = (const float4*)(g_Wm2t + (size_t)n * MLPD);
                    const float4* dv = (const float4*)(s_dh + row * MLPD);
#pragma unroll 2
                    for (int k4 = 0; k4 < MLPD / 4; k4++) {
                        float4 w = wt[k4];
                        float4 x = dv[k4];
                        a0 += x.x * w.x; a0 += x.y * w.y; a0 += x.z * w.z; a0 += x.w * w.w;
                    }
                    s_h[row * HDIM + n] = fmaxf(a0, 0.f);
                }
            }
            for (int i = tid; i < 6 * EDIM; i += NT) s_x[i] = g_decin[row0 * EDIM + i];
            __syncthreads();
            // LSTM gates: 1 column per thread (tid = gate col), transposed weights
            {
                float a[6];
                float bb = b_ih[tid] + b_hh[tid];
#pragma unroll
                for (int r = 0; r < 6; r++) a[r] = bb;
                const float4* wx = (const float4*)(g_Wiht + (size_t)tid * EDIM);
                for (int k4 = 0; k4 < EDIM / 4; k4++) {
                    float4 w = wx[k4];
#pragma unroll
                    for (int r = 0; r < 6; r++) {
                        float4 xv = *(const float4*)(s_x + r * EDIM + k4 * 4);
                        a[r] += w.x * xv.x; a[r] += w.y * xv.y;
                        a[r] += w.z * xv.z; a[r] += w.w * xv.w;
                    }
                }
                const float4* wh = (const float4*)(g_Whht + (size_t)tid * HDIM);
                for (int k4 = 0; k4 < HDIM / 4; k4++) {
                    float4 w = wh[k4];
#pragma unroll
                    for (int r = 0; r < 6; r++) {
                        float4 hv = *(const float4*)(s_h + r * HDIM + k4 * 4);
                        a[r] += w.x * hv.x; a[r] += w.y * hv.y;
                        a[r] += w.z * hv.z; a[r] += w.w * hv.w;
                    }
                }
#pragma unroll
                for (int r = 0; r < 6; r++) s_g[r * G4 + tid] = a[r];
            }
            __syncthreads();
            for (int i = tid; i < 6 * HDIM; i += NT) {
                int r = i >> 7, hc = i & 127;
                const float* gr = s_g + r * G4;
                float ig = sigf(gr[hc]);
                float fg = sigf(gr[HDIM + hc]);
                float gg = tanhf(gr[2 * HDIM + hc]);
                float og = sigf(gr[3 * HDIM + hc]);
                float c = fg * g_c[(row0 + r) * HDIM + hc] + ig * gg;
                float hn = og * tanhf(c);
                g_c[(row0 + r) * HDIM + hc] = c;
                g_hmid[(row0 + r) * HDIM + hc] = hn;
                s_h[r * HDIM + hc] = hn;
            }
            __syncthreads();
            if (tid < 12) {
                int r = tid >> 1, d = tid & 1;
                float a = b_hp[d];
                for (int k = 0; k < HDIM; k++) a += s_h[r * HDIM + k] * W_hp[k * 2 + d];
                s_rel[tid] = a;
                out[(size_t)t * BATCH * 2 + row0 * 2 + tid] = a;
                g_pos[row0 * 2 + tid] = a + g_pos[row0 * 2 + tid];
            }
            __syncthreads();
            for (int i = tid; i < 6 * EDIM; i += NT) {
                int r = i >> 6, e = i & 63;
                g_decin[(row0 + r) * EDIM + e] =
                    b_se[e] + s_rel[r * 2] * W_se[e] + s_rel[r * 2 + 1] * W_se[EDIM + e];
            }
            // hterm: 1 column per thread
            {
                float a[6];
                float cb = g_cb[tid];
#pragma unroll
                for (int r = 0; r < 6; r++) a[r] = cb;
                const float4* wp = (const float4*)(g_Wp1t + (size_t)tid * HDIM);
                for (int k4 = 0; k4 < HDIM / 4; k4++) {
                    float4 w = wp[k4];
#pragma unroll
                    for (int r = 0; r < 6; r++) {
                        float4 hv = *(const float4*)(s_h + r * HDIM + k4 * 4);
                        a[r] += w.x * hv.x; a[r] += w.y * hv.y;
                        a[r] += w.z * hv.z; a[r] += w.w * hv.w;
                    }
                }
#pragma unroll
                for (int r = 0; r < 6; r++) g_hterm[(row0 + r) * P1D + tid] = a[r];
            }
        }
        grid_bar(base + ++bc);

        // ========== phase B: fused layer1 + GEMM + pool (16 warps, 32x32 tiles) =======
        {
            const uint32_t sbA = sb + SMB_A;
            const uint32_t sbB = sb + SMB_B;
            __half* Dsm = (__half*)(smraw + SMB_D);
            float* sdx = (float*)(smraw + SMB_D);
            float* sdy = sdx + 128;
            int* sjr = (int*)(sdy + 128);
            float* sm0 = (float*)(sjr + 128);
            float* sm1 = sm0 + 512;
            const int wm = (wid & 3) * 32, wn = (wid >> 2) * 32;
            const int R0 = bx * 128;

#pragma unroll
            for (int p = 0; p < 2; p++) {
                int idx = tid + p * NT;
                int row = idx >> 3, seg = idx & 7;
                uint32_t dst = sbB + (uint32_t)row * 128 +
                               (((uint32_t)seg * 16) ^ ((uint32_t)(row & 7) << 4));
                cp_async16(dst, g_Wp2t + (size_t)row * P1D + seg * 8);
            }
            CP_COMMIT();

            if (tid < 128) {
                int gr = R0 + tid;
                int s = gr / 576;
                int rem = gr - s * 576;
                int i = rem / 24;
                int j = rem - i * 24;
                int jped = s * 24 + j, iped = s * 24 + i;
                sjr[tid] = jped;
                sdx[tid] = g_pos[jped * 2] - g_pos[iped * 2];
                sdy[tid] = g_pos[jped * 2 + 1] - g_pos[iped * 2 + 1];
            }
            for (int k = tid; k < P1D; k += NT) { sm0[k] = g_M2[k]; sm1[k] = g_M2[P1D + k]; }
            __syncthreads();

            for (int p = 0; p < 16; p++) {
                int idx = tid + p * NT;
                int r = idx >> 6, sg = idx & 63;
                int k0 = sg * 8;
                const float4* hp = (const float4*)(g_hterm + (size_t)sjr[r] * P1D + k0);
                float4 h0 = hp[0], h1 = hp[1];
                float dx = sdx[r], dy = sdy[r];
                float4 a0 = *(const float4*)(sm0 + k0), a1 = *(const float4*)(sm0 + k0 + 4);
                float4 c0 = *(const float4*)(sm1 + k0), c1 = *(const float4*)(sm1 + k0 + 4);
                __half2 o[4];
                o[0] = __floats2half2_rn(fmaxf(h0.x + dx * a0.x + dy * c0.x, 0.f),
                                         fmaxf(h0.y + dx * a0.y + dy * c0.y, 0.f));
                o[1] = __floats2half2_rn(fmaxf(h0.z + dx * a0.z + dy * c0.z, 0.f),
                                         fmaxf(h0.w + dx * a0.w + dy * c0.w, 0.f));
                o[2] = __floats2half2_rn(fmaxf(h1.x + dx * a1.x + dy * c1.x, 0.f),
                                         fmaxf(h1.y + dx * a1.y + dy * c1.y, 0.f));
                o[3] = __floats2half2_rn(fmaxf(h1.z + dx * a1.z + dy * c1.z, 0.f),
                                         fmaxf(h1.w + dx * a1.w + dy * c1.w, 0.f));
                uint32_t off = (uint32_t)r * 1024 + (((uint32_t)sg * 16) ^ ((uint32_t)(r & 7) << 4));
                *(uint4*)(smraw + SMB_A + off) = *(uint4*)o;
            }
            __syncthreads();

            int buf = 0;
            for (int nt2 = 0; nt2 < 8; nt2++) {
                float acc[2][4][4] = {};
                for (int ck = 0; ck < 8; ck++) {
                    const int c = nt2 * 8 + ck + 1;
                    if (c < 64) {
                        const int nnt = c >> 3, nck = c & 7;
                        const __half* src = g_Wp2t + (size_t)nnt * 128 * P1D + nck * 64;
                        uint32_t dstb = sbB + (uint32_t)(buf ^ 1) * 16384;
#pragma unroll
                        for (int p = 0; p < 2; p++) {
                            int idx = tid + p * NT;
                            int row = idx >> 3, seg = idx & 7;
                            cp_async16(dstb + (uint32_t)row * 128 +
                                           (((uint32_t)seg * 16) ^ ((uint32_t)(row & 7) << 4)),
                                       src + (size_t)row * P1D + seg * 8);
                        }
                        CP_COMMIT();
                        CP_WAIT(1);
                    } else {
                        CP_WAIT(0);
                    }
                    __syncthreads();
                    const uint32_t sBc = sbB + (uint32_t)buf * 16384;
                    const uint32_t kbase = (uint32_t)(ck * 64 + mkof) * 2;
#pragma unroll
                    for (int kk = 0; kk < 64; kk += 16) {
                        const uint32_t kbA = kbase + (uint32_t)kk * 2;
                        const uint32_t kbB = (uint32_t)(kk + mkof) * 2;
                        uint32_t af[2][4], bf[4][2];
#pragma unroll
                        for (int mi = 0; mi < 2; mi++) {
                            uint32_t addr = sbA + (uint32_t)(wm + mi * 16 + mrow) * 1024 + (kbA ^ swz);
                            ldsm_x4(af[mi], addr);
                        }
#pragma unroll
                        for (int pi = 0; pi < 2; pi++) {
                            uint32_t r[4];
                            uint32_t addr = sBc + (uint32_t)(wn + pi * 16 + mrow) * 128 + (kbB ^ swz);
                            ldsm_x4(r, addr);
                            bf[2 * pi][0] = r[0]; bf[2 * pi][1] = r[2];
                            bf[2 * pi + 1][0] = r[1]; bf[2 * pi + 1][1] = r[3];
                        }
#pragma unroll
                        for (int mi = 0; mi < 2; mi++)
#pragma unroll
                            for (int ni = 0; ni < 4; ni++)
                                mma_f16(acc[mi][ni], af[mi], bf[ni]);
                    }
                    __syncthreads();
                    buf ^= 1;
                }
                const int n0 = nt2 * 128;
#pragma unroll
                for (int mi = 0; mi < 2; mi++)
#pragma unroll
                    for (int ni = 0; ni < 4; ni++) {
                        int r = wm + mi * 16 + gid;
                        int col = wn + ni * 8 + 2 * tig;
                        float bv0 = bp2[n0 + col], bv1 = bp2[n0 + col + 1];
                        *(__half2*)(Dsm + r * DP + col) =
                            __floats2half2_rn(fmaxf(acc[mi][ni][0] + bv0, 0.f),
                                              fmaxf(acc[mi][ni][1] + bv1, 0.f));
                        *(__half2*)(Dsm + (r + 8) * DP + col) =
                            __floats2half2_rn(fmaxf(acc[mi][ni][2] + bv0, 0.f),
                                              fmaxf(acc[mi][ni][3] + bv1, 0.f));
                    }
                __syncthreads();
                const int ped0 = R0 / NP;
                const int pedN = (R0 + 127) / NP - ped0 + 1;
                for (int it = tid; it < pedN * 128; it += NT) {
                    int pl = it >> 7, col = it & 127;
                    int gp = ped0 + pl;
                    int rs = gp * NP - R0, re = rs + NP;
                    if (rs < 0) rs = 0;
                    if (re > 128) re = 128;
                    float v = 0.f;
                    for (int rr = rs; rr < re; rr++) v = fmaxf(v, __half2float(Dsm[rr * DP + col]));
                    atomicMax((int*)&g_pool[(size_t)gp * BNK + n0 + col], __float_as_int(v));
                }
                __syncthreads();
            }
        }
        grid_bar(base + ++bc);

        // ========== phase C: mlp1 (fp16 mma, 16 warps 16x32 tiles, dbuf B) ============
        if (bx < 96) {
            __half* As = (__half*)smraw;               // 64*KP
            __half* Bs = As + 64 * KP;                 // 2 x 128*KP
            const uint32_t sbA = smem_u32(As);
            const uint32_t sbB = smem_u32(Bs);
            const int wm = (wid & 3) * 16, wn = (wid >> 2) * 32;
            const int n0 = (bx & 7) * 128, m0 = (bx >> 3) * 64;
            const __half* Bg = g_Wm1t + (size_t)n0 * KTOT;
            const int lrow = tid >> 3;                 // 0..63
            const int lcol = (tid & 7) * 8;
            const uint32_t bstage = 128 * KP * 2;

#pragma unroll
            for (int p = 0; p < 2; p++) {
                int row = lrow + p * 64;
                cp_async16(sbB + (uint32_t)(row * KP + lcol) * 2,
                           Bg + (size_t)row * KTOT + lcol);
            }
            CP_COMMIT();

            float acc[4][4] = {};
            int buf = 0;
            for (int ci = 0; ci < KTOT / GP_KC; ci++) {
                const int kc = ci * GP_KC;
                if (ci + 1 < KTOT / GP_KC) {
                    const int kn = kc + GP_KC;
#pragma unroll
                    for (int p = 0; p < 2; p++) {
                        int row = lrow + p * 64;
                        cp_async16(sbB + (uint32_t)(buf ^ 1) * bstage +
                                       (uint32_t)(row * KP + lcol) * 2,
                                   Bg + (size_t)row * KTOT + kn + lcol);
                    }
                    CP_COMMIT();
                }
                // A: 64 rows x 8 halves per thread (512 threads exactly)
                {
                    int row = lrow;
                    int k = kc + lcol;
                    const float* src = (k < HDIM) ? (g_hmid + (size_t)(m0 + row) * HDIM + k)
                                                  : (g_pool + (size_t)(m0 + row) * BNK + (k - HDIM));
                    float4 v0 = ((const float4*)src)[0];
                    float4 v1 = ((const float4*)src)[1];
                    __half2* da = (__half2*)(As + row * KP + lcol);
                    da[0] = __floats2half2_rn(v0.x, v0.y);
                    da[1] = __floats2half2_rn(v0.z, v0.w);
                    da[2] = __floats2half2_rn(v1.x, v1.y);
                    da[3] = __floats2half2_rn(v1.z, v1.w);
                }
                if (ci + 1 < KTOT / GP_KC) { CP_WAIT(1); } else { CP_WAIT(0); }
                __syncthreads();
                const uint32_t sBc = sbB + (uint32_t)buf * bstage;
#pragma unroll
                for (int kk = 0; kk < GP_KC; kk += 16) {
                    uint32_t af[4], bf[4][2];
                    {
                        uint32_t addr = sbA + (uint32_t)((wm + mrow) * KP + kk + mkof) * 2;
                        ldsm_x4(af, addr);
                    }
#pragma unroll
                    for (int pi = 0; pi < 2; pi++) {
                        uint32_t r[4];
                        uint32_t addr = sBc + (uint32_t)((wn + pi * 16 + mrow) * KP + kk + mkof) * 2;
                        ldsm_x4(r, addr);
                        bf[2 * pi][0] = r[0]; bf[2 * pi][1] = r[2];
                        bf[2 * pi + 1][0] = r[1]; bf[2 * pi + 1][1] = r[3];
                    }
#pragma unroll
                    for (int ni = 0; ni < 4; ni++)
                        mma_f16(acc[ni], af, bf[ni]);
                }
                __syncthreads();
                buf ^= 1;
            }
#pragma unroll
            for (int ni = 0; ni < 4; ni++) {
                int r = m0 + wm + gid;
                int c = n0 + wn + ni * 8 + 2 * tig;
                float bv0 = bm1[c], bv1 = bm1[c + 1];
                g_dh[(size_t)r * MLPD + c]           = fmaxf(acc[ni][0] + bv0, 0.f);
                g_dh[(size_t)r * MLPD + c + 1]       = fmaxf(acc[ni][1] + bv1, 0.f);
                g_dh[(size_t)(r + 8) * MLPD + c]     = fmaxf(acc[ni][2] + bv0, 0.f);
                g_dh[(size_t)(r + 8) * MLPD + c + 1] = fmaxf(acc[ni][3] + bv1, 0.f);
            }
        }
        grid_bar(base + ++bc);
    }

    // ===== final: mlp2 of step-12 dh -> h_fin, written straight to out ===============
    if (bx < 128) {
        const int row0 = bx * 6;
        float* s_dh = (float*)smraw;
        const float4* src = (const float4*)(g_dh + (size_t)row0 * MLPD);
        float4* dst = (float4*)s_dh;
        for (int i = tid; i < 6 * MLPD / 4; i += NT) dst[i] = src[i];
        __syncthreads();
        float* ob = out + (size_t)TSTEPS * BATCH * 2;
        for (int i = tid; i < 6 * HDIM; i += NT) {
            int row = i >> 7, n = i & 127;
            float a0 = bm2[n];
            const float4* wt = (const float4*)(g_Wm2t + (size_t)n * MLPD);
            const float4* dv = (const float4*)(s_dh + row * MLPD);
#pragma unroll 2
            for (int k4 = 0; k4 < MLPD / 4; k4++) {
                float4 w = wt[k4];
                float4 x = dv[k4];
                a0 += x.x * w.x; a0 += x.y * w.y; a0 += x.z * w.z; a0 += x.w * w.w;
            }
            ob[(row0 + row) * HDIM + n] = fmaxf(a0, 0.f);
        }
    }
}

// ---------------- launch ----------------
extern "C" void kernel_launch(void* const* d_in, const int* in_sizes, int n_in,
                              void* d_out, int out_size) {
    const float* last_pos     = (const float*)d_in[0];
    const float* last_pos_rel = (const float*)d_in[1];
    const float* h0   = (const float*)d_in[2];
    const float* c0   = (const float*)d_in[3];
    /* d_in[4] = seq_start_end (uniform scenes; unused) */
    const float* W_se = (const float*)d_in[5];
    const float* b_se = (const float*)d_in[6];
    const float* W_ih = (const float*)d_in[7];
    const float* b_ih = (const float*)d_in[8];
    const float* W_hh = (const float*)d_in[9];
    const float* b_hh = (const float*)d_in[10];
    const float* W_hp = (const float*)d_in[11];
    const float* b_hp = (const float*)d_in[12];
    const float* W_pse = (const float*)d_in[13];
    const float* b_pse = (const float*)d_in[14];
    const float* W_p1 = (const float*)d_in[15];
    const float* b_p1 = (const float*)d_in[16];
    const float* W_p2 = (const float*)d_in[17];
    const float* b_p2 = (const float*)d_in[18];
    const float* W_m1 = (const float*)d_in[19];
    const float* b_m1 = (const float*)d_in[20];
    const float* W_m2 = (const float*)d_in[21];
    const float* b_m2 = (const float*)d_in[22];
    float* out = (float*)d_out;

    cudaFuncSetAttribute(decoder_persistent, cudaFuncAttributeMaxDynamicSharedMemorySize, SMEM_GP);

    setup_kernel<<<96, 256>>>(last_pos, last_pos_rel, h0, c0, W_se, b_se, W_pse, b_pse,
                              W_p1, b_p1, W_p2, W_m1, W_m2, W_ih, W_hh);
    decoder_persistent<<<NCTA, NT, SMEM_GP>>>(b_ih, b_hh, W_hp, b_hp, W_se, b_se,
                                              b_p2, b_m1, b_m2, out);
}

// round 14
// speedup vs baseline: 1.6335x; 1.6335x over previous
#include <cuda_runtime.h>
#include <cuda_fp16.h>
#include <math.h>
#include <stdint.h>

#define BATCH 768
#define NS 32
#define NP 24
#define EDIM 64
#define HDIM 128
#define G4 512      // 4*HDIM
#define P1D 512     // pool hidden
#define BNK 1024
#define MLPD 1024
#define KTOT (HDIM + BNK)   // 1152
#define TSTEPS 12
#define NCTA 144

// ---------------- scratch (static device memory; no allocations) ----------------
__device__ float g_pos[BATCH * 2];
__device__ float g_decin[BATCH * EDIM];
__device__ float g_h[BATCH * HDIM];
__device__ float g_c[BATCH * HDIM];
__device__ float g_hmid[BATCH * HDIM];
__device__ float g_hterm[BATCH * P1D];
__device__ float g_pool[(size_t)BATCH * BNK];
__device__ float g_dh[(size_t)BATCH * MLPD];
__device__ float g_M2[2 * P1D];
__device__ float g_cb[P1D];
__device__ __half g_Wp2t[(size_t)BNK * P1D];        // W_p2^T fp16
__device__ __half g_Wm1t[(size_t)MLPD * KTOT];      // W_m1^T fp16
__device__ __half2 g_WihP[(EDIM / 2) * G4];         // k-pair packed fp16
__device__ __half2 g_WhhP[(HDIM / 2) * G4];
__device__ __half2 g_Wp1P[(HDIM / 2) * P1D];        // W_p1[64:192] packed
__device__ __half2 g_Wm2P[(MLPD / 2) * HDIM];
__device__ unsigned g_bar_count;
__device__ unsigned g_bar_sense;

__device__ __forceinline__ float sigf(float x) { return 1.f / (1.f + expf(-x)); }

__device__ __forceinline__ void mma_f16(float* d, const uint32_t* a, const uint32_t* b) {
    asm volatile(
        "mma.sync.aligned.m16n8k16.row.col.f32.f16.f16.f32 "
        "{%0,%1,%2,%3}, {%4,%5,%6,%7}, {%8,%9}, {%0,%1,%2,%3};"
        : "+f"(d[0]), "+f"(d[1]), "+f"(d[2]), "+f"(d[3])
        : "r"(a[0]), "r"(a[1]), "r"(a[2]), "r"(a[3]), "r"(b[0]), "r"(b[1]));
}

__device__ __forceinline__ void ldsm_x4(uint32_t* r, uint32_t saddr) {
    asm volatile("ldmatrix.sync.aligned.m8n8.x4.shared.b16 {%0,%1,%2,%3}, [%4];"
                 : "=r"(r[0]), "=r"(r[1]), "=r"(r[2]), "=r"(r[3]) : "r"(saddr));
}

__device__ __forceinline__ uint32_t smem_u32(const void* p) {
    uint32_t a;
    asm("{ .reg .u64 t; cvta.to.shared.u64 t, %1; cvt.u32.u64 %0, t; }" : "=r"(a) : "l"(p));
    return a;
}
__device__ __forceinline__ void cp_async16(uint32_t saddr, const void* g) {
    asm volatile("cp.async.cg.shared.global [%0], [%1], 16;" :: "r"(saddr), "l"(g));
}
#define CP_COMMIT() asm volatile("cp.async.commit_group;" ::: "memory")
#define CP_WAIT(n)  asm volatile("cp.async.wait_group %0;" :: "n"(n) : "memory")

// ---- software grid barrier (all NCTA CTAs resident by construction) ----
__device__ __forceinline__ void grid_bar(unsigned target) {
    __syncthreads();
    if (threadIdx.x == 0) {
        __threadfence();
        unsigned old = atomicAdd(&g_bar_count, 1);
        if (old == NCTA - 1) {
            g_bar_count = 0;
            __threadfence();
            atomicAdd(&g_bar_sense, 1);
        } else {
            while ((int)(*(volatile unsigned*)&g_bar_sense - target) < 0)
                __nanosleep(64);
        }
        __threadfence();
    }
    __syncthreads();
}

// ---------------- setup ----------------
__global__ void setup_kernel(const float* __restrict__ last_pos,
                             const float* __restrict__ last_pos_rel,
                             const float* __restrict__ h0, const float* __restrict__ c0,
                             const float* __restrict__ W_se, const float* __restrict__ b_se,
                             const float* __restrict__ W_pse, const float* __restrict__ b_pse,
                             const float* __restrict__ W_p1, const float* __restrict__ b_p1,
                             const float* __restrict__ W_p2, const float* __restrict__ W_m1,
                             const float* __restrict__ W_m2,
                             const float* __restrict__ W_ih, const float* __restrict__ W_hh) {
    int tid = blockIdx.x * blockDim.x + threadIdx.x;
    int nt = gridDim.x * blockDim.x;
    for (int i = tid; i < BATCH * 2; i += nt) g_pos[i] = last_pos[i];
    for (int i = tid; i < BATCH * HDIM; i += nt) { g_h[i] = h0[i]; g_c[i] = c0[i]; }
    for (int i = tid; i < BATCH * EDIM; i += nt) {
        int b = i >> 6, e = i & 63;
        g_decin[i] = b_se[e] + last_pos_rel[b * 2] * W_se[e] + last_pos_rel[b * 2 + 1] * W_se[EDIM + e];
    }
    for (int i = tid; i < 2 * P1D; i += nt) {
        int d = i >> 9, t = i & 511;
        float a = 0.f;
        for (int e = 0; e < EDIM; e++) a += W_pse[d * EDIM + e] * W_p1[e * P1D + t];
        g_M2[i] = a;
    }
    for (int i = tid; i < P1D; i += nt) {
        float a = b_p1[i];
        for (int e = 0; e < EDIM; e++) a += b_pse[e] * W_p1[e * P1D + i];
        g_cb[i] = a;
    }
    for (int i = tid; i < BNK * P1D; i += nt) {
        int n = i / P1D, k = i % P1D;
        g_Wp2t[i] = __float2half_rn(W_p2[(size_t)k * BNK + n]);
    }
    for (int i = tid; i < MLPD * KTOT; i += nt) {
        int n = i / KTOT, k = i % KTOT;
        g_Wm1t[i] = __float2half_rn(W_m1[(size_t)k * MLPD + n]);
    }
    for (int i = tid; i < (EDIM / 2) * G4; i += nt) {
        int k2 = i / G4, g = i % G4;
        g_WihP[i] = __floats2half2_rn(W_ih[(size_t)(2 * k2) * G4 + g],
                                      W_ih[(size_t)(2 * k2 + 1) * G4 + g]);
    }
    for (int i = tid; i < (HDIM / 2) * G4; i += nt) {
        int k2 = i / G4, g = i % G4;
        g_WhhP[i] = __floats2half2_rn(W_hh[(size_t)(2 * k2) * G4 + g],
                                      W_hh[(size_t)(2 * k2 + 1) * G4 + g]);
    }
    for (int i = tid; i < (HDIM / 2) * P1D; i += nt) {
        int k2 = i / P1D, n = i % P1D;
        g_Wp1P[i] = __floats2half2_rn(W_p1[(size_t)(EDIM + 2 * k2) * P1D + n],
                                      W_p1[(size_t)(EDIM + 2 * k2 + 1) * P1D + n]);
    }
    for (int i = tid; i < (MLPD / 2) * HDIM; i += nt) {
        int k2 = i / HDIM, n = i % HDIM;
        g_Wm2P[i] = __floats2half2_rn(W_m2[(size_t)(2 * k2) * HDIM + n],
                                      W_m2[(size_t)(2 * k2 + 1) * HDIM + n]);
    }
}

// ---------------- persistent all-steps kernel ----------------
#define SMB_A 0
#define SMB_B 131072
#define SMB_D 163840
#define SMEM_GP (163840 + 128 * 136 * 2)   // 198656
#define DP 136
#define GP_KC 64
#define KP 72

__global__ __launch_bounds__(256) void decoder_persistent(
    const float* __restrict__ b_ih, const float* __restrict__ b_hh,
    const float* __restrict__ W_hp, const float* __restrict__ b_hp,
    const float* __restrict__ W_se, const float* __restrict__ b_se,
    const float* __restrict__ bp2, const float* __restrict__ bm1,
    const float* __restrict__ bm2,
    float* __restrict__ out) {
    extern __shared__ char smraw[];
    const int tid = threadIdx.x;
    const int bx = blockIdx.x;
    const int wid = tid >> 5, lane = tid & 31;
    const int gid = lane >> 2, tig = lane & 3;
    const int q = lane >> 3;
    const int mrow = (q & 1) * 8 + (lane & 7);
    const int mkof = (q >> 1) * 8;
    const uint32_t swz = (uint32_t)(lane & 7) << 4;
    const uint32_t sb = smem_u32(smraw);

    unsigned base = *(volatile unsigned*)&g_bar_sense;
    unsigned bc = 0;

    for (int t = 0; t < TSTEPS; t++) {
        // early prefetch of phase-B's first weight chunk (SMB_B region is idle in phase A)
        {
            const uint32_t sbB = sb + SMB_B;
#pragma unroll
            for (int p = 0; p < 4; p++) {
                int idx = tid + p * 256;
                int row = idx >> 3, seg = idx & 7;
                uint32_t dst = sbB + (uint32_t)row * 128 +
                               (((uint32_t)seg * 16) ^ ((uint32_t)(row & 7) << 4));
                cp_async16(dst, g_Wp2t + (size_t)row * P1D + seg * 8);
            }
            CP_COMMIT();
        }

        // ===== phase A: [mlp2 of prev dh ->] h, LSTM, hidden2pos, pos, dec_in, hterm ====
        if (bx < 128) {
            const int row0 = bx * 6;
            float* s_dh = (float*)smraw;             // 6*1024
            float* s_h = s_dh + 6 * MLPD;            // 6*128
            float* s_x = s_h + 6 * HDIM;             // 6*64
            float* s_g = s_x + 6 * EDIM;             // 6*512
            float* s_rel = s_g + 6 * G4;             // 12
            {
                float4 z = make_float4(0.f, 0.f, 0.f, 0.f);
                float4* pz = (float4*)(g_pool + (size_t)row0 * BNK);
                for (int i = tid; i < 6 * BNK / 4; i += 256) pz[i] = z;
            }
            if (t == 0) {
                for (int i = tid; i < 6 * HDIM; i += 256) s_h[i] = g_h[row0 * HDIM + i];
            } else {
                const float4* src = (const float4*)(g_dh + (size_t)row0 * MLPD);
                float4* dst = (float4*)s_dh;
                for (int i = tid; i < 6 * MLPD / 4; i += 256) dst[i] = src[i];
                __syncthreads();
                int n = tid & 127, rg = tid >> 7;     // rows rg*3..rg*3+2
                float bb = bm2[n];
                float a0 = bb, a1 = bb, a2 = bb;
                const float* d0 = s_dh + (rg * 3 + 0) * MLPD;
                const float* d1 = s_dh + (rg * 3 + 1) * MLPD;
                const float* d2 = s_dh + (rg * 3 + 2) * MLPD;
#pragma unroll 4
                for (int k2 = 0; k2 < MLPD / 2; k2++) {
                    __half2 w = g_Wm2P[k2 * HDIM + n];
                    float wl = __low2float(w), wh = __high2float(w);
                    float2 x0 = *(const float2*)(d0 + 2 * k2);
                    float2 x1 = *(const float2*)(d1 + 2 * k2);
                    float2 x2 = *(const float2*)(d2 + 2 * k2);
                    a0 += x0.x * wl; a0 += x0.y * wh;
                    a1 += x1.x * wl; a1 += x1.y * wh;
                    a2 += x2.x * wl; a2 += x2.y * wh;
                }
                s_h[(rg * 3 + 0) * HDIM + n] = fmaxf(a0, 0.f);
                s_h[(rg * 3 + 1) * HDIM + n] = fmaxf(a1, 0.f);
                s_h[(rg * 3 + 2) * HDIM + n] = fmaxf(a2, 0.f);
            }
            for (int i = tid; i < 6 * EDIM; i += 256) s_x[i] = g_decin[row0 * EDIM + i];
            __syncthreads();
            // LSTM gates: cols tid and tid+256, packed fp16 weights, fp32 accumulate
            {
                float a0[6], a1[6];
                float bb0 = b_ih[tid] + b_hh[tid];
                float bb1 = b_ih[tid + 256] + b_hh[tid + 256];
#pragma unroll
                for (int r = 0; r < 6; r++) { a0[r] = bb0; a1[r] = bb1; }
#pragma unroll 4
                for (int k2 = 0; k2 < EDIM / 2; k2++) {
                    __half2 w0h = g_WihP[k2 * G4 + tid];
                    __half2 w1h = g_WihP[k2 * G4 + tid + 256];
                    float w0l = __low2float(w0h), w0u = __high2float(w0h);
                    float w1l = __low2float(w1h), w1u = __high2float(w1h);
#pragma unroll
                    for (int r = 0; r < 6; r++) {
                        float2 xv = *(const float2*)(s_x + r * EDIM + 2 * k2);
                        a0[r] += w0l * xv.x; a0[r] += w0u * xv.y;
                        a1[r] += w1l * xv.x; a1[r] += w1u * xv.y;
                    }
                }
#pragma unroll 4
                for (int k2 = 0; k2 < HDIM / 2; k2++) {
                    __half2 w0h = g_WhhP[k2 * G4 + tid];
                    __half2 w1h = g_WhhP[k2 * G4 + tid + 256];
                    float w0l = __low2float(w0h), w0u = __high2float(w0h);
                    float w1l = __low2float(w1h), w1u = __high2float(w1h);
#pragma unroll
                    for (int r = 0; r < 6; r++) {
                        float2 hv = *(const float2*)(s_h + r * HDIM + 2 * k2);
                        a0[r] += w0l * hv.x; a0[r] += w0u * hv.y;
                        a1[r] += w1l * hv.x; a1[r] += w1u * hv.y;
                    }
                }
#pragma unroll
                for (int r = 0; r < 6; r++) {
                    s_g[r * G4 + tid] = a0[r];
                    s_g[r * G4 + tid + 256] = a1[r];
                }
            }
            __syncthreads();
            for (int i = tid; i < 6 * HDIM; i += 256) {
                int r = i >> 7, hc = i & 127;
                const float* gr = s_g + r * G4;
                float ig = sigf(gr[hc]);
                float fg = sigf(gr[HDIM + hc]);
                float gg = tanhf(gr[2 * HDIM + hc]);
                float og = sigf(gr[3 * HDIM + hc]);
                float c = fg * g_c[(row0 + r) * HDIM + hc] + ig * gg;
                float hn = og * tanhf(c);
                g_c[(row0 + r) * HDIM + hc] = c;
                g_hmid[(row0 + r) * HDIM + hc] = hn;
                s_h[r * HDIM + hc] = hn;
            }
            __syncthreads();
            if (tid < 12) {
                int r = tid >> 1, d = tid & 1;
                float a = b_hp[d];
                for (int k = 0; k < HDIM; k++) a += s_h[r * HDIM + k] * W_hp[k * 2 + d];
                s_rel[tid] = a;
                out[(size_t)t * BATCH * 2 + row0 * 2 + tid] = a;
                g_pos[row0 * 2 + tid] = a + g_pos[row0 * 2 + tid];
            }
            __syncthreads();
            for (int i = tid; i < 6 * EDIM; i += 256) {
                int r = i >> 6, e = i & 63;
                g_decin[(row0 + r) * EDIM + e] =
                    b_se[e] + s_rel[r * 2] * W_se[e] + s_rel[r * 2 + 1] * W_se[EDIM + e];
            }
            // hterm: cols tid, tid+256, packed fp16 weights
            {
                float a0[6], a1[6];
                float cb0 = g_cb[tid], cb1 = g_cb[tid + 256];
#pragma unroll
                for (int r = 0; r < 6; r++) { a0[r] = cb0; a1[r] = cb1; }
#pragma unroll 4
                for (int k2 = 0; k2 < HDIM / 2; k2++) {
                    __half2 w0h = g_Wp1P[k2 * P1D + tid];
                    __half2 w1h = g_Wp1P[k2 * P1D + tid + 256];
                    float w0l = __low2float(w0h), w0u = __high2float(w0h);
                    float w1l = __low2float(w1h), w1u = __high2float(w1h);
#pragma unroll
                    for (int r = 0; r < 6; r++) {
                        float2 hv = *(const float2*)(s_h + r * HDIM + 2 * k2);
                        a0[r] += w0l * hv.x; a0[r] += w0u * hv.y;
                        a1[r] += w1l * hv.x; a1[r] += w1u * hv.y;
                    }
                }
#pragma unroll
                for (int r = 0; r < 6; r++) {
                    g_hterm[(row0 + r) * P1D + tid] = a0[r];
                    g_hterm[(row0 + r) * P1D + tid + 256] = a1[r];
                }
            }
        }
        grid_bar(base + ++bc);

        // ========== phase B: fused layer1 + GEMM + pool (double-buffered B) ===========
        {
            const uint32_t sbA = sb + SMB_A;
            const uint32_t sbB = sb + SMB_B;
            __half* Dsm = (__half*)(smraw + SMB_D);
            float* sdx = (float*)(smraw + SMB_D);
            float* sdy = sdx + 128;
            int* sjr = (int*)(sdy + 128);
            float* sm0 = (float*)(sjr + 128);
            float* sm1 = sm0 + 512;
            const int wm = (wid & 1) * 64, wn = (wid >> 1) * 32;
            const int R0 = bx * 128;

            if (tid < 128) {
                int gr = R0 + tid;
                int s = gr / 576;
                int rem = gr - s * 576;
                int i = rem / 24;
                int j = rem - i * 24;
                int jped = s * 24 + j, iped = s * 24 + i;
                sjr[tid] = jped;
                sdx[tid] = g_pos[jped * 2] - g_pos[iped * 2];
                sdy[tid] = g_pos[jped * 2 + 1] - g_pos[iped * 2 + 1];
            }
            for (int k = tid; k < P1D; k += 256) { sm0[k] = g_M2[k]; sm1[k] = g_M2[P1D + k]; }
            __syncthreads();

            for (int p = 0; p < 32; p++) {
                int idx = tid + p * 256;
                int r = idx >> 6, sg = idx & 63;
                int k0 = sg * 8;
                const float4* hp = (const float4*)(g_hterm + (size_t)sjr[r] * P1D + k0);
                float4 h0 = hp[0], h1 = hp[1];
                float dx = sdx[r], dy = sdy[r];
                float4 a0 = *(const float4*)(sm0 + k0), a1 = *(const float4*)(sm0 + k0 + 4);
                float4 c0 = *(const float4*)(sm1 + k0), c1 = *(const float4*)(sm1 + k0 + 4);
                __half2 o[4];
                o[0] = __floats2half2_rn(fmaxf(h0.x + dx * a0.x + dy * c0.x, 0.f),
                                         fmaxf(h0.y + dx * a0.y + dy * c0.y, 0.f));
                o[1] = __floats2half2_rn(fmaxf(h0.z + dx * a0.z + dy * c0.z, 0.f),
                                         fmaxf(h0.w + dx * a0.w + dy * c0.w, 0.f));
                o[2] = __floats2half2_rn(fmaxf(h1.x + dx * a1.x + dy * c1.x, 0.f),
                                         fmaxf(h1.y + dx * a1.y + dy * c1.y, 0.f));
                o[3] = __floats2half2_rn(fmaxf(h1.z + dx * a1.z + dy * c1.z, 0.f),
                                         fmaxf(h1.w + dx * a1.w + dy * c1.w, 0.f));
                uint32_t off = (uint32_t)r * 1024 + (((uint32_t)sg * 16) ^ ((uint32_t)(r & 7) << 4));
                *(uint4*)(smraw + SMB_A + off) = *(uint4*)o;
            }
            __syncthreads();

            int buf = 0;
            for (int nt = 0; nt < 8; nt++) {
                float acc[4][4][4] = {};
                for (int ck = 0; ck < 8; ck++) {
                    const int c = nt * 8 + ck + 1;
                    if (c < 64) {
                        const int nnt = c >> 3, nck = c & 7;
                        const __half* src = g_Wp2t + (size_t)nnt * 128 * P1D + nck * 64;
                        uint32_t dstb = sbB + (uint32_t)(buf ^ 1) * 16384;
#pragma unroll
                        for (int p = 0; p < 4; p++) {
                            int idx = tid + p * 256;
                            int row = idx >> 3, seg = idx & 7;
                            cp_async16(dstb + (uint32_t)row * 128 +
                                           (((uint32_t)seg * 16) ^ ((uint32_t)(row & 7) << 4)),
                                       src + (size_t)row * P1D + seg * 8);
                        }
                        CP_COMMIT();
                        CP_WAIT(1);
                    } else {
                        CP_WAIT(0);
                    }
                    __syncthreads();
                    const uint32_t sBc = sbB + (uint32_t)buf * 16384;
                    const uint32_t kbase = (uint32_t)(ck * 64 + mkof) * 2;
#pragma unroll
                    for (int kk = 0; kk < 64; kk += 16) {
                        const uint32_t kbA = kbase + (uint32_t)kk * 2;
                        const uint32_t kbB = (uint32_t)(kk + mkof) * 2;
                        uint32_t af[4][4], bf[4][2];
#pragma unroll
                        for (int mi = 0; mi < 4; mi++) {
                            uint32_t addr = sbA + (uint32_t)(wm + mi * 16 + mrow) * 1024 + (kbA ^ swz);
                            ldsm_x4(af[mi], addr);
                        }
#pragma unroll
                        for (int pi = 0; pi < 2; pi++) {
                            uint32_t r[4];
                            uint32_t addr = sBc + (uint32_t)(wn + pi * 16 + mrow) * 128 + (kbB ^ swz);
                            ldsm_x4(r, addr);
                            bf[2 * pi][0] = r[0]; bf[2 * pi][1] = r[2];
                            bf[2 * pi + 1][0] = r[1]; bf[2 * pi + 1][1] = r[3];
                        }
#pragma unroll
                        for (int mi = 0; mi < 4; mi++)
#pragma unroll
                            for (int ni = 0; ni < 4; ni++)
                                mma_f16(acc[mi][ni], af[mi], bf[ni]);
                    }
                    __syncthreads();
                    buf ^= 1;
                }
                const int n0 = nt * 128;
#pragma unroll
                for (int mi = 0; mi < 4; mi++)
#pragma unroll
                    for (int ni = 0; ni < 4; ni++) {
                        int r = wm + mi * 16 + gid;
                        int col = wn + ni * 8 + 2 * tig;
                        float bv0 = bp2[n0 + col], bv1 = bp2[n0 + col + 1];
                        *(__half2*)(Dsm + r * DP + col) =
                            __floats2half2_rn(fmaxf(acc[mi][ni][0] + bv0, 0.f),
                                              fmaxf(acc[mi][ni][1] + bv1, 0.f));
                        *(__half2*)(Dsm + (r + 8) * DP + col) =
                            __floats2half2_rn(fmaxf(acc[mi][ni][2] + bv0, 0.f),
                                              fmaxf(acc[mi][ni][3] + bv1, 0.f));
                    }
                __syncthreads();
                const int ped0 = R0 / NP;
                const int pedN = (R0 + 127) / NP - ped0 + 1;
                for (int it = tid; it < pedN * 128; it += 256) {
                    int pl = it >> 7, col = it & 127;
                    int gp = ped0 + pl;
                    int rs = gp * NP - R0, re = rs + NP;
                    if (rs < 0) rs = 0;
                    if (re > 128) re = 128;
                    float v = 0.f;
                    for (int rr = rs; rr < re; rr++) v = fmaxf(v, __half2float(Dsm[rr * DP + col]));
                    atomicMax((int*)&g_pool[(size_t)gp * BNK + n0 + col], __float_as_int(v));
                }
                __syncthreads();
            }
        }
        grid_bar(base + ++bc);

        // ================= phase C: mlp1 (fp16 mma, double-buffered B) ================
        if (bx < 96) {
            __half* As = (__half*)smraw;               // 64*KP
            __half* Bs = As + 64 * KP;                 // 2 x 128*KP
            const uint32_t sbA = smem_u32(As);
            const uint32_t sbB = smem_u32(Bs);
            const int wm = (wid & 1) * 32, wn = (wid >> 1) * 32;
            const int n0 = (bx & 7) * 128, m0 = (bx >> 3) * 64;
            const __half* Bg = g_Wm1t + (size_t)n0 * KTOT;
            const int lrow = tid >> 3;
            const int lcol = (tid & 7) * 8;
            const uint32_t bstage = 128 * KP * 2;

#pragma unroll
            for (int p = 0; p < 4; p++) {
                int row = lrow + p * 32;
                cp_async16(sbB + (uint32_t)(row * KP + lcol) * 2,
                           Bg + (size_t)row * KTOT + lcol);
            }
            CP_COMMIT();

            float acc[2][4][4] = {};
            int buf = 0;
            for (int ci = 0; ci < KTOT / GP_KC; ci++) {
                const int kc = ci * GP_KC;
                if (ci + 1 < KTOT / GP_KC) {
                    const int kn = kc + GP_KC;
#pragma unroll
                    for (int p = 0; p < 4; p++) {
                        int row = lrow + p * 32;
                        cp_async16(sbB + (uint32_t)(buf ^ 1) * bstage +
                                       (uint32_t)(row * KP + lcol) * 2,
                                   Bg + (size_t)row * KTOT + kn + lcol);
                    }
                    CP_COMMIT();
                }
#pragma unroll
                for (int p = 0; p < 2; p++) {
                    int row = lrow + p * 32;
                    int k = kc + lcol;
                    const float* src = (k < HDIM) ? (g_hmid + (size_t)(m0 + row) * HDIM + k)
                                                  : (g_pool + (size_t)(m0 + row) * BNK + (k - HDIM));
                    float4 v0 = ((const float4*)src)[0];
                    float4 v1 = ((const float4*)src)[1];
                    __half2* da = (__half2*)(As + row * KP + lcol);
                    da[0] = __floats2half2_rn(v0.x, v0.y);
                    da[1] = __floats2half2_rn(v0.z, v0.w);
                    da[2] = __floats2half2_rn(v1.x, v1.y);
                    da[3] = __floats2half2_rn(v1.z, v1.w);
                }
                if (ci + 1 < KTOT / GP_KC) { CP_WAIT(1); } else { CP_WAIT(0); }
                __syncthreads();
                const uint32_t sBc = sbB + (uint32_t)buf * bstage;
#pragma unroll
                for (int kk = 0; kk < GP_KC; kk += 16) {
                    uint32_t af[2][4], bf[4][2];
#pragma unroll
                    for (int mi = 0; mi < 2; mi++) {
                        uint32_t addr = sbA + (uint32_t)((wm + mi * 16 + mrow) * KP + kk + mkof) * 2;
                        ldsm_x4(af[mi], addr);
                    }
#pragma unroll
                    for (int pi = 0; pi < 2; pi++) {
                        uint32_t r[4];
                        uint32_t addr = sBc + (uint32_t)((wn + pi * 16 + mrow) * KP + kk + mkof) * 2;
                        ldsm_x4(r, addr);
                        bf[2 * pi][0] = r[0]; bf[2 * pi][1] = r[2];
                        bf[2 * pi + 1][0] = r[1]; bf[2 * pi + 1][1] = r[3];
                    }
#pragma unroll
                    for (int mi = 0; mi < 2; mi++)
#pragma unroll
                        for (int ni = 0; ni < 4; ni++)
                            mma_f16(acc[mi][ni], af[mi], bf[ni]);
                }
                __syncthreads();
                buf ^= 1;
            }
#pragma unroll
            for (int mi = 0; mi < 2; mi++)
#pragma unroll
                for (int ni = 0; ni < 4; ni++) {
                    int r = m0 + wm + mi * 16 + gid;
                    int c = n0 + wn + ni * 8 + 2 * tig;
                    float bv0 = bm1[c], bv1 = bm1[c + 1];
                    g_dh[(size_t)r * MLPD + c]           = fmaxf(acc[mi][ni][0] + bv0, 0.f);
                    g_dh[(size_t)r * MLPD + c + 1]       = fmaxf(acc[mi][ni][1] + bv1, 0.f);
                    g_dh[(size_t)(r + 8) * MLPD + c]     = fmaxf(acc[mi][ni][2] + bv0, 0.f);
                    g_dh[(size_t)(r + 8) * MLPD + c + 1] = fmaxf(acc[mi][ni][3] + bv1, 0.f);
                }
        } else {
            CP_WAIT(0);   // retire the early prefetch for CTAs that skip phase C
        }
        grid_bar(base + ++bc);
    }

    // ===== final: mlp2 of step-12 dh -> h_fin, written straight to out ===============
    if (bx < 128) {
        const int row0 = bx * 6;
        float* s_dh = (float*)smraw;
        const float4* src = (const float4*)(g_dh + (size_t)row0 * MLPD);
        float4* dst = (float4*)s_dh;
        for (int i = tid; i < 6 * MLPD / 4; i += 256) dst[i] = src[i];
        __syncthreads();
        int n = tid & 127, rg = tid >> 7;
        float bb = bm2[n];
        float a0 = bb, a1 = bb, a2 = bb;
        const float* d0 = s_dh + (rg * 3 + 0) * MLPD;
        const float* d1 = s_dh + (rg * 3 + 1) * MLPD;
        const float* d2 = s_dh + (rg * 3 + 2) * MLPD;
#pragma unroll 4
        for (int k2 = 0; k2 < MLPD / 2; k2++) {
            __half2 w = g_Wm2P[k2 * HDIM + n];
            float wl = __low2float(w), wh = __high2float(w);
            float2 x0 = *(const float2*)(d0 + 2 * k2);
            float2 x1 = *(const float2*)(d1 + 2 * k2);
            float2 x2 = *(const float2*)(d2 + 2 * k2);
            a0 += x0.x * wl; a0 += x0.y * wh;
            a1 += x1.x * wl; a1 += x1.y * wh;
            a2 += x2.x * wl; a2 += x2.y * wh;
        }
        float* ob = out + (size_t)TSTEPS * BATCH * 2;
        ob[(row0 + rg * 3 + 0) * HDIM + n] = fmaxf(a0, 0.f);
        ob[(row0 + rg * 3 + 1) * HDIM + n] = fmaxf(a1, 0.f);
        ob[(row0 + rg * 3 + 2) * HDIM + n] = fmaxf(a2, 0.f);
    }
}

// ---------------- launch ----------------
extern "C" void kernel_launch(void* const* d_in, const int* in_sizes, int n_in,
                              void* d_out, int out_size) {
    const float* last_pos     = (const float*)d_in[0];
    const float* last_pos_rel = (const float*)d_in[1];
    const float* h0   = (const float*)d_in[2];
    const float* c0   = (const float*)d_in[3];
    /* d_in[4] = seq_start_end (uniform scenes; unused) */
    const float* W_se = (const float*)d_in[5];
    const float* b_se = (const float*)d_in[6];
    const float* W_ih = (const float*)d_in[7];
    const float* b_ih = (const float*)d_in[8];
    const float* W_hh = (const float*)d_in[9];
    const float* b_hh = (const float*)d_in[10];
    const float* W_hp = (const float*)d_in[11];
    const float* b_hp = (const float*)d_in[12];
    const float* W_pse = (const float*)d_in[13];
    const float* b_pse = (const float*)d_in[14];
    const float* W_p1 = (const float*)d_in[15];
    const float* b_p1 = (const float*)d_in[16];
    const float* W_p2 = (const float*)d_in[17];
    const float* b_p2 = (const float*)d_in[18];
    const float* W_m1 = (const float*)d_in[19];
    const float* b_m1 = (const float*)d_in[20];
    const float* W_m2 = (const float*)d_in[21];
    const float* b_m2 = (const float*)d_in[22];
    float* out = (float*)d_out;

    cudaFuncSetAttribute(decoder_persistent, cudaFuncAttributeMaxDynamicSharedMemorySize, SMEM_GP);

    setup_kernel<<<96, 256>>>(last_pos, last_pos_rel, h0, c0, W_se, b_se, W_pse, b_pse,
                              W_p1, b_p1, W_p2, W_m1, W_m2, W_ih, W_hh);
    decoder_persistent<<<NCTA, 256, SMEM_GP>>>(b_ih, b_hh, W_hp, b_hp, W_se, b_se,
                                               b_p2, b_m1, b_m2, out);
}

// round 15
// speedup vs baseline: 1.6742x; 1.0249x over previous
#include <cuda_runtime.h>
#include <cuda_fp16.h>
#include <math.h>
#include <stdint.h>

#define BATCH 768
#define NS 32
#define NP 24
#define EDIM 64
#define HDIM 128
#define G4 512      // 4*HDIM
#define P1D 512     // pool hidden
#define BNK 1024
#define MLPD 1024
#define KTOT (HDIM + BNK)   // 1152
#define TSTEPS 12
#define NCTA 288
#define MB 64               // rows per phase-B block

// ---------------- scratch (static device memory; no allocations) ----------------
__device__ float g_pos[BATCH * 2];
__device__ float g_decin[BATCH * EDIM];
__device__ float g_h[BATCH * HDIM];
__device__ float g_c[BATCH * HDIM];
__device__ float g_hmid[BATCH * HDIM];
__device__ float g_hterm[BATCH * P1D];
__device__ float g_pool[(size_t)BATCH * BNK];
__device__ float g_dh[(size_t)BATCH * MLPD];
__device__ float g_M2[2 * P1D];
__device__ float g_cb[P1D];
__device__ __half g_Wp2t[(size_t)BNK * P1D];        // W_p2^T fp16
__device__ __half g_Wm1t[(size_t)MLPD * KTOT];      // W_m1^T fp16
__device__ __half2 g_WihP[(EDIM / 2) * G4];         // k-pair packed fp16
__device__ __half2 g_WhhP[(HDIM / 2) * G4];
__device__ __half2 g_Wp1P[(HDIM / 2) * P1D];        // W_p1[64:192] packed
__device__ __half2 g_Wm2P[(MLPD / 2) * HDIM];
__device__ unsigned g_bar_cnt[512];                 // group g at g*16, root at 480
__device__ unsigned g_bar_sense;

__device__ __forceinline__ float sigf(float x) { return 1.f / (1.f + expf(-x)); }

__device__ __forceinline__ void mma_f16(float* d, const uint32_t* a, const uint32_t* b) {
    asm volatile(
        "mma.sync.aligned.m16n8k16.row.col.f32.f16.f16.f32 "
        "{%0,%1,%2,%3}, {%4,%5,%6,%7}, {%8,%9}, {%0,%1,%2,%3};"
        : "+f"(d[0]), "+f"(d[1]), "+f"(d[2]), "+f"(d[3])
        : "r"(a[0]), "r"(a[1]), "r"(a[2]), "r"(a[3]), "r"(b[0]), "r"(b[1]));
}

__device__ __forceinline__ void ldsm_x4(uint32_t* r, uint32_t saddr) {
    asm volatile("ldmatrix.sync.aligned.m8n8.x4.shared.b16 {%0,%1,%2,%3}, [%4];"
                 : "=r"(r[0]), "=r"(r[1]), "=r"(r[2]), "=r"(r[3]) : "r"(saddr));
}

__device__ __forceinline__ uint32_t smem_u32(const void* p) {
    uint32_t a;
    asm("{ .reg .u64 t; cvta.to.shared.u64 t, %1; cvt.u32.u64 %0, t; }" : "=r"(a) : "l"(p));
    return a;
}
__device__ __forceinline__ void cp_async16(uint32_t saddr, const void* g) {
    asm volatile("cp.async.cg.shared.global [%0], [%1], 16;" :: "r"(saddr), "l"(g));
}
#define CP_COMMIT() asm volatile("cp.async.commit_group;" ::: "memory")
#define CP_WAIT(n)  asm volatile("cp.async.wait_group %0;" :: "n"(n) : "memory")

// ---- two-level tree barrier: 18 groups of 16 CTAs; monotonic counters, replay-safe ----
__device__ __forceinline__ void grid_bar(unsigned target) {
    __syncthreads();
    if (threadIdx.x == 0) {
        __threadfence();
        int g = blockIdx.x >> 4;                     // 0..17
        unsigned old = atomicAdd(&g_bar_cnt[g * 16], 1u);
        bool released = false;
        if ((old + 1u) % 16u == 0u) {
            unsigned o2 = atomicAdd(&g_bar_cnt[480], 1u);
            if ((o2 + 1u) % 18u == 0u) {
                __threadfence();
                atomicAdd(&g_bar_sense, 1u);
                released = true;
            }
        }
        if (!released) {
            while ((int)(*(volatile unsigned*)&g_bar_sense - target) < 0)
                __nanosleep(32);
        }
        __threadfence();
    }
    __syncthreads();
}

// ---------------- setup ----------------
__global__ void setup_kernel(const float* __restrict__ last_pos,
                             const float* __restrict__ last_pos_rel,
                             const float* __restrict__ h0, const float* __restrict__ c0,
                             const float* __restrict__ W_se, const float* __restrict__ b_se,
                             const float* __restrict__ W_pse, const float* __restrict__ b_pse,
                             const float* __restrict__ W_p1, const float* __restrict__ b_p1,
                             const float* __restrict__ W_p2, const float* __restrict__ W_m1,
                             const float* __restrict__ W_m2,
                             const float* __restrict__ W_ih, const float* __restrict__ W_hh) {
    int tid = blockIdx.x * blockDim.x + threadIdx.x;
    int nt = gridDim.x * blockDim.x;
    for (int i = tid; i < BATCH * 2; i += nt) g_pos[i] = last_pos[i];
    for (int i = tid; i < BATCH * HDIM; i += nt) { g_h[i] = h0[i]; g_c[i] = c0[i]; }
    for (int i = tid; i < BATCH * EDIM; i += nt) {
        int b = i >> 6, e = i & 63;
        g_decin[i] = b_se[e] + last_pos_rel[b * 2] * W_se[e] + last_pos_rel[b * 2 + 1] * W_se[EDIM + e];
    }
    for (int i = tid; i < 2 * P1D; i += nt) {
        int d = i >> 9, t = i & 511;
        float a = 0.f;
        for (int e = 0; e < EDIM; e++) a += W_pse[d * EDIM + e] * W_p1[e * P1D + t];
        g_M2[i] = a;
    }
    for (int i = tid; i < P1D; i += nt) {
        float a = b_p1[i];
        for (int e = 0; e < EDIM; e++) a += b_pse[e] * W_p1[e * P1D + i];
        g_cb[i] = a;
    }
    for (int i = tid; i < BNK * P1D; i += nt) {
        int n = i / P1D, k = i % P1D;
        g_Wp2t[i] = __float2half_rn(W_p2[(size_t)k * BNK + n]);
    }
    for (int i = tid; i < MLPD * KTOT; i += nt) {
        int n = i / KTOT, k = i % KTOT;
        g_Wm1t[i] = __float2half_rn(W_m1[(size_t)k * MLPD + n]);
    }
    for (int i = tid; i < (EDIM / 2) * G4; i += nt) {
        int k2 = i / G4, g = i % G4;
        g_WihP[i] = __floats2half2_rn(W_ih[(size_t)(2 * k2) * G4 + g],
                                      W_ih[(size_t)(2 * k2 + 1) * G4 + g]);
    }
    for (int i = tid; i < (HDIM / 2) * G4; i += nt) {
        int k2 = i / G4, g = i % G4;
        g_WhhP[i] = __floats2half2_rn(W_hh[(size_t)(2 * k2) * G4 + g],
                                      W_hh[(size_t)(2 * k2 + 1) * G4 + g]);
    }
    for (int i = tid; i < (HDIM / 2) * P1D; i += nt) {
        int k2 = i / P1D, n = i % P1D;
        g_Wp1P[i] = __floats2half2_rn(W_p1[(size_t)(EDIM + 2 * k2) * P1D + n],
                                      W_p1[(size_t)(EDIM + 2 * k2 + 1) * P1D + n]);
    }
    for (int i = tid; i < (MLPD / 2) * HDIM; i += nt) {
        int k2 = i / HDIM, n = i % HDIM;
        g_Wm2P[i] = __floats2half2_rn(W_m2[(size_t)(2 * k2) * HDIM + n],
                                      W_m2[(size_t)(2 * k2 + 1) * HDIM + n]);
    }
}

// ---------------- persistent all-steps kernel (288 CTAs, 2/SM) ----------------
#define SMB_A 0               // 64 rows x 512 halves = 65536 B
#define SMB_B 65536           // 2 stages x 16384
#define SMB_D 98304           // 32 rows x 136 halves = 8704 B
#define SMEM_GP 107008
#define DP 136
#define GP_KC 64
#define KP 72

__global__ void __launch_bounds__(256, 2) decoder_persistent(
    const float* __restrict__ b_ih, const float* __restrict__ b_hh,
    const float* __restrict__ W_hp, const float* __restrict__ b_hp,
    const float* __restrict__ W_se, const float* __restrict__ b_se,
    const float* __restrict__ bp2, const float* __restrict__ bm1,
    const float* __restrict__ bm2,
    float* __restrict__ out) {
    extern __shared__ char smraw[];
    const int tid = threadIdx.x;
    const int bx = blockIdx.x;
    const int wid = tid >> 5, lane = tid & 31;
    const int gid = lane >> 2, tig = lane & 3;
    const int q = lane >> 3;
    const int mrow = (q & 1) * 8 + (lane & 7);
    const int mkof = (q >> 1) * 8;
    const uint32_t swz = (uint32_t)(lane & 7) << 4;
    const uint32_t sb = smem_u32(smraw);

    unsigned base = *(volatile unsigned*)&g_bar_sense;
    unsigned bc = 0;

    for (int t = 0; t < TSTEPS; t++) {
        // early prefetch of phase-B's first weight chunk (SMB_B idle during phase A)
        {
            const uint32_t sbB = sb + SMB_B;
#pragma unroll
            for (int p = 0; p < 4; p++) {
                int idx = tid + p * 256;
                int row = idx >> 3, seg = idx & 7;
                uint32_t dst = sbB + (uint32_t)row * 128 +
                               (((uint32_t)seg * 16) ^ ((uint32_t)(row & 7) << 4));
                cp_async16(dst, g_Wp2t + (size_t)row * P1D + seg * 8);
            }
            CP_COMMIT();
        }

        // ===== phase A (192 CTAs x 4 rows): mlp2(prev dh) -> h, LSTM, pos, dec_in, hterm
        if (bx < 192) {
            const int row0 = bx * 4;
            float* s_dh = (float*)smraw;             // 4*1024
            float* s_h = s_dh + 4 * MLPD;            // 4*128
            float* s_x = s_h + 4 * HDIM;             // 4*64
            float* s_g = s_x + 4 * EDIM;             // 4*512
            float* s_rel = s_g + 4 * G4;             // 8
            {
                float4 z = make_float4(0.f, 0.f, 0.f, 0.f);
                float4* pz = (float4*)(g_pool + (size_t)row0 * BNK);
                for (int i = tid; i < 4 * BNK / 4; i += 256) pz[i] = z;
            }
            if (t == 0) {
                for (int i = tid; i < 4 * HDIM; i += 256) s_h[i] = g_h[row0 * HDIM + i];
            } else {
                const float4* src = (const float4*)(g_dh + (size_t)row0 * MLPD);
                float4* dst = (float4*)s_dh;
                for (int i = tid; i < 4 * MLPD / 4; i += 256) dst[i] = src[i];
                __syncthreads();
                int n = tid & 127, rg = tid >> 7;     // rows rg*2, rg*2+1
                float bb = bm2[n];
                float a0 = bb, a1 = bb;
                const float* d0 = s_dh + (rg * 2 + 0) * MLPD;
                const float* d1 = s_dh + (rg * 2 + 1) * MLPD;
#pragma unroll 4
                for (int k2 = 0; k2 < MLPD / 2; k2++) {
                    __half2 w = g_Wm2P[k2 * HDIM + n];
                    float wl = __low2float(w), wh = __high2float(w);
                    float2 x0 = *(const float2*)(d0 + 2 * k2);
                    float2 x1 = *(const float2*)(d1 + 2 * k2);
                    a0 += x0.x * wl; a0 += x0.y * wh;
                    a1 += x1.x * wl; a1 += x1.y * wh;
                }
                s_h[(rg * 2 + 0) * HDIM + n] = fmaxf(a0, 0.f);
                s_h[(rg * 2 + 1) * HDIM + n] = fmaxf(a1, 0.f);
            }
            for (int i = tid; i < 4 * EDIM; i += 256) s_x[i] = g_decin[row0 * EDIM + i];
            __syncthreads();
            // LSTM gates: cols tid, tid+256, packed fp16 weights, fp32 accumulate
            {
                float a0[4], a1[4];
                float bb0 = b_ih[tid] + b_hh[tid];
                float bb1 = b_ih[tid + 256] + b_hh[tid + 256];
#pragma unroll
                for (int r = 0; r < 4; r++) { a0[r] = bb0; a1[r] = bb1; }
#pragma unroll 4
                for (int k2 = 0; k2 < EDIM / 2; k2++) {
                    __half2 w0h = g_WihP[k2 * G4 + tid];
                    __half2 w1h = g_WihP[k2 * G4 + tid + 256];
                    float w0l = __low2float(w0h), w0u = __high2float(w0h);
                    float w1l = __low2float(w1h), w1u = __high2float(w1h);
#pragma unroll
                    for (int r = 0; r < 4; r++) {
                        float2 xv = *(const float2*)(s_x + r * EDIM + 2 * k2);
                        a0[r] += w0l * xv.x; a0[r] += w0u * xv.y;
                        a1[r] += w1l * xv.x; a1[r] += w1u * xv.y;
                    }
                }
#pragma unroll 4
                for (int k2 = 0; k2 < HDIM / 2; k2++) {
                    __half2 w0h = g_WhhP[k2 * G4 + tid];
                    __half2 w1h = g_WhhP[k2 * G4 + tid + 256];
                    float w0l = __low2float(w0h), w0u = __high2float(w0h);
                    float w1l = __low2float(w1h), w1u = __high2float(w1h);
#pragma unroll
                    for (int r = 0; r < 4; r++) {
                        float2 hv = *(const float2*)(s_h + r * HDIM + 2 * k2);
                        a0[r] += w0l * hv.x; a0[r] += w0u * hv.y;
                        a1[r] += w1l * hv.x; a1[r] += w1u * hv.y;
                    }
                }
#pragma unroll
                for (int r = 0; r < 4; r++) {
                    s_g[r * G4 + tid] = a0[r];
                    s_g[r * G4 + tid + 256] = a1[r];
                }
            }
            __syncthreads();
            for (int i = tid; i < 4 * HDIM; i += 256) {
                int r = i >> 7, hc = i & 127;
                const float* gr = s_g + r * G4;
                float ig = sigf(gr[hc]);
                float fg = sigf(gr[HDIM + hc]);
                float gg = tanhf(gr[2 * HDIM + hc]);
                float og = sigf(gr[3 * HDIM + hc]);
                float c = fg * g_c[(row0 + r) * HDIM + hc] + ig * gg;
                float hn = og * tanhf(c);
                g_c[(row0 + r) * HDIM + hc] = c;
                g_hmid[(row0 + r) * HDIM + hc] = hn;
                s_h[r * HDIM + hc] = hn;
            }
            __syncthreads();
            if (tid < 8) {
                int r = tid >> 1, d = tid & 1;
                float a = b_hp[d];
                for (int k = 0; k < HDIM; k++) a += s_h[r * HDIM + k] * W_hp[k * 2 + d];
                s_rel[tid] = a;
                out[(size_t)t * BATCH * 2 + row0 * 2 + tid] = a;
                g_pos[row0 * 2 + tid] = a + g_pos[row0 * 2 + tid];
            }
            __syncthreads();
            if (tid < 4 * EDIM) {
                int r = tid >> 6, e = tid & 63;
                g_decin[(row0 + r) * EDIM + e] =
                    b_se[e] + s_rel[r * 2] * W_se[e] + s_rel[r * 2 + 1] * W_se[EDIM + e];
            }
            // hterm: cols tid, tid+256, packed fp16 weights
            {
                float a0[4], a1[4];
                float cb0 = g_cb[tid], cb1 = g_cb[tid + 256];
#pragma unroll
                for (int r = 0; r < 4; r++) { a0[r] = cb0; a1[r] = cb1; }
#pragma unroll 4
                for (int k2 = 0; k2 < HDIM / 2; k2++) {
                    __half2 w0h = g_Wp1P[k2 * P1D + tid];
                    __half2 w1h = g_Wp1P[k2 * P1D + tid + 256];
                    float w0l = __low2float(w0h), w0u = __high2float(w0h);
                    float w1l = __low2float(w1h), w1u = __high2float(w1h);
#pragma unroll
                    for (int r = 0; r < 4; r++) {
                        float2 hv = *(const float2*)(s_h + r * HDIM + 2 * k2);
                        a0[r] += w0l * hv.x; a0[r] += w0u * hv.y;
                        a1[r] += w1l * hv.x; a1[r] += w1u * hv.y;
                    }
                }
#pragma unroll
                for (int r = 0; r < 4; r++) {
                    g_hterm[(row0 + r) * P1D + tid] = a0[r];
                    g_hterm[(row0 + r) * P1D + tid + 256] = a1[r];
                }
            }
        }
        grid_bar(base + ++bc);

        // ========== phase B (288 CTAs x 64 rows): layer1 + GEMM + pool ==========
        {
            const uint32_t sbA = sb + SMB_A;
            const uint32_t sbB = sb + SMB_B;
            __half* Dsm = (__half*)(smraw + SMB_D);
            float* sdx = (float*)(smraw + SMB_D);     // meta overlays D (dead after A-fill)
            float* sdy = sdx + MB;
            int* sjr = (int*)(sdy + MB);
            float* sm0 = (float*)(sjr + MB);
            float* sm1 = sm0 + 512;
            const int wm = (wid & 1) * 32, wn = (wid >> 1) * 32;
            const int R0 = bx * MB;

            if (tid < MB) {
                int gr = R0 + tid;
                int s = gr / 576;
                int rem = gr - s * 576;
                int i = rem / 24;
                int j = rem - i * 24;
                int jped = s * 24 + j, iped = s * 24 + i;
                sjr[tid] = jped;
                sdx[tid] = g_pos[jped * 2] - g_pos[iped * 2];
                sdy[tid] = g_pos[jped * 2 + 1] - g_pos[iped * 2 + 1];
            }
            for (int k = tid; k < P1D; k += 256) { sm0[k] = g_M2[k]; sm1[k] = g_M2[P1D + k]; }
            __syncthreads();

            // A fill: 64 rows x 512 halves
            for (int p = 0; p < 16; p++) {
                int idx = tid + p * 256;
                int r = idx >> 6, sg = idx & 63;
                int k0 = sg * 8;
                const float4* hp = (const float4*)(g_hterm + (size_t)sjr[r] * P1D + k0);
                float4 h0 = hp[0], h1 = hp[1];
                float dx = sdx[r], dy = sdy[r];
                float4 a0 = *(const float4*)(sm0 + k0), a1 = *(const float4*)(sm0 + k0 + 4);
                float4 c0 = *(const float4*)(sm1 + k0), c1 = *(const float4*)(sm1 + k0 + 4);
                __half2 o[4];
                o[0] = __floats2half2_rn(fmaxf(h0.x + dx * a0.x + dy * c0.x, 0.f),
                                         fmaxf(h0.y + dx * a0.y + dy * c0.y, 0.f));
                o[1] = __floats2half2_rn(fmaxf(h0.z + dx * a0.z + dy * c0.z, 0.f),
                                         fmaxf(h0.w + dx * a0.w + dy * c0.w, 0.f));
                o[2] = __floats2half2_rn(fmaxf(h1.x + dx * a1.x + dy * c1.x, 0.f),
                                         fmaxf(h1.y + dx * a1.y + dy * c1.y, 0.f));
                o[3] = __floats2half2_rn(fmaxf(h1.z + dx * a1.z + dy * c1.z, 0.f),
                                         fmaxf(h1.w + dx * a1.w + dy * c1.w, 0.f));
                uint32_t off = (uint32_t)r * 1024 + (((uint32_t)sg * 16) ^ ((uint32_t)(r & 7) << 4));
                *(uint4*)(smraw + SMB_A + off) = *(uint4*)o;
            }
            __syncthreads();

            int buf = 0;
            for (int nt = 0; nt < 8; nt++) {
                float acc[2][4][4] = {};
                for (int ck = 0; ck < 8; ck++) {
                    const int c = nt * 8 + ck + 1;
                    if (c < 64) {
                        const int nnt = c >> 3, nck = c & 7;
                        const __half* src = g_Wp2t + (size_t)nnt * 128 * P1D + nck * 64;
                        uint32_t dstb = sbB + (uint32_t)(buf ^ 1) * 16384;
#pragma unroll
                        for (int p = 0; p < 4; p++) {
                            int idx = tid + p * 256;
                            int row = idx >> 3, seg = idx & 7;
                            cp_async16(dstb + (uint32_t)row * 128 +
                                           (((uint32_t)seg * 16) ^ ((uint32_t)(row & 7) << 4)),
                                       src + (size_t)row * P1D + seg * 8);
                        }
                        CP_COMMIT();
                        CP_WAIT(1);
                    } else {
                        CP_WAIT(0);
                    }
                    __syncthreads();
                    const uint32_t sBc = sbB + (uint32_t)buf * 16384;
                    const uint32_t kbase = (uint32_t)(ck * 64 + mkof) * 2;
#pragma unroll
                    for (int kk = 0; kk < 64; kk += 16) {
                        const uint32_t kbA = kbase + (uint32_t)kk * 2;
                        const uint32_t kbB = (uint32_t)(kk + mkof) * 2;
                        uint32_t af[2][4], bf[4][2];
#pragma unroll
                        for (int mi = 0; mi < 2; mi++) {
                            uint32_t addr = sbA + (uint32_t)(wm + mi * 16 + mrow) * 1024 + (kbA ^ swz);
                            ldsm_x4(af[mi], addr);
                        }
#pragma unroll
                        for (int pi = 0; pi < 2; pi++) {
                            uint32_t r[4];
                            uint32_t addr = sBc + (uint32_t)(wn + pi * 16 + mrow) * 128 + (kbB ^ swz);
                            ldsm_x4(r, addr);
                            bf[2 * pi][0] = r[0]; bf[2 * pi][1] = r[2];
                            bf[2 * pi + 1][0] = r[1]; bf[2 * pi + 1][1] = r[3];
                        }
#pragma unroll
                        for (int mi = 0; mi < 2; mi++)
#pragma unroll
                            for (int ni = 0; ni < 4; ni++)
                                mma_f16(acc[mi][ni], af[mi], bf[ni]);
                    }
                    __syncthreads();
                    buf ^= 1;
                }
                // ---- epilogue for n-tile nt, two 32-row halves ----
                const int n0 = nt * 128;
                const int ped0 = R0 / NP;
                const int pedN = (R0 + MB - 1) / NP - ped0 + 1;   // <= 4
#pragma unroll
                for (int hh = 0; hh < 2; hh++) {
                    if ((wid & 1) == hh) {
#pragma unroll
                        for (int mi = 0; mi < 2; mi++)
#pragma unroll
                            for (int ni = 0; ni < 4; ni++) {
                                int r2 = mi * 16 + gid;
                                int col = wn + ni * 8 + 2 * tig;
                                float bv0 = bp2[n0 + col], bv1 = bp2[n0 + col + 1];
                                *(__half2*)(Dsm + r2 * DP + col) =
                                    __floats2half2_rn(fmaxf(acc[mi][ni][0] + bv0, 0.f),
                                                      fmaxf(acc[mi][ni][1] + bv1, 0.f));
                                *(__half2*)(Dsm + (r2 + 8) * DP + col) =
                                    __floats2half2_rn(fmaxf(acc[mi][ni][2] + bv0, 0.f),
                                                      fmaxf(acc[mi][ni][3] + bv1, 0.f));
                            }
                    }
                    __syncthreads();
                    const int rowlo = hh * 32, rowhi = rowlo + 32;
                    for (int it = tid; it < pedN * 128; it += 256) {
                        int pl = it >> 7, col = it & 127;
                        int gp = ped0 + pl;
                        int rs = gp * NP - R0, re = rs + NP;
                        if (rs < rowlo) rs = rowlo;
                        if (re > rowhi) re = rowhi;
                        if (rs < re) {
                            float v = 0.f;
                            for (int rr = rs; rr < re; rr++)
                                v = fmaxf(v, __half2float(Dsm[(rr - rowlo) * DP + col]));
                            atomicMax((int*)&g_pool[(size_t)gp * BNK + n0 + col], __float_as_int(v));
                        }
                    }
                    __syncthreads();
                }
            }
        }
        grid_bar(base + ++bc);

        // ========== phase C (192 CTAs): mlp1, tile 32 x 128, dbuf B ==========
        if (bx < 192) {
            __half* As = (__half*)smraw;               // 32*KP
            __half* Bs = As + 32 * KP;                 // 2 x 128*KP
            const uint32_t sbA = smem_u32(As);
            const uint32_t sbB = smem_u32(Bs);
            const int wm = (wid & 1) * 16, wn = (wid >> 1) * 32;
            const int n0 = (bx & 7) * 128, m0 = (bx >> 3) * 32;
            const __half* Bg = g_Wm1t + (size_t)n0 * KTOT;
            const int lrow = tid >> 3;                 // 0..31
            const int lcol = (tid & 7) * 8;
            const uint32_t bstage = 128 * KP * 2;

#pragma unroll
            for (int p = 0; p < 4; p++) {
                int row = lrow + p * 32;
                cp_async16(sbB + (uint32_t)(row * KP + lcol) * 2,
                           Bg + (size_t)row * KTOT + lcol);
            }
            CP_COMMIT();

            float acc[4][4] = {};
            int buf = 0;
            for (int ci = 0; ci < KTOT / GP_KC; ci++) {
                const int kc = ci * GP_KC;
                if (ci + 1 < KTOT / GP_KC) {
                    const int kn = kc + GP_KC;
#pragma unroll
                    for (int p = 0; p < 4; p++) {
                        int row = lrow + p * 32;
                        cp_async16(sbB + (uint32_t)(buf ^ 1) * bstage +
                                       (uint32_t)(row * KP + lcol) * 2,
                                   Bg + (size_t)row * KTOT + kn + lcol);
                    }
                    CP_COMMIT();
                }
                // A: 32 rows, exactly one vec8 per thread
                {
                    int row = lrow;
                    int k = kc + lcol;
                    const float* src = (k < HDIM) ? (g_hmid + (size_t)(m0 + row) * HDIM + k)
                                                  : (g_pool + (size_t)(m0 + row) * BNK + (k - HDIM));
                    float4 v0 = ((const float4*)src)[0];
                    float4 v1 = ((const float4*)src)[1];
                    __half2* da = (__half2*)(As + row * KP + lcol);
                    da[0] = __floats2half2_rn(v0.x, v0.y);
                    da[1] = __floats2half2_rn(v0.z, v0.w);
                    da[2] = __floats2half2_rn(v1.x, v1.y);
                    da[3] = __floats2half2_rn(v1.z, v1.w);
                }
                if (ci + 1 < KTOT / GP_KC) { CP_WAIT(1); } else { CP_WAIT(0); }
                __syncthreads();
                const uint32_t sBc = sbB + (uint32_t)buf * bstage;
#pragma unroll
                for (int kk = 0; kk < GP_KC; kk += 16) {
                    uint32_t af[4], bf[4][2];
                    {
                        uint32_t addr = sbA + (uint32_t)((wm + mrow) * KP + kk + mkof) * 2;
                        ldsm_x4(af, addr);
                    }
#pragma unroll
                    for (int pi = 0; pi < 2; pi++) {
                        uint32_t r[4];
                        uint32_t addr = sBc + (uint32_t)((wn + pi * 16 + mrow) * KP + kk + mkof) * 2;
                        ldsm_x4(r, addr);
                        bf[2 * pi][0] = r[0]; bf[2 * pi][1] = r[2];
                        bf[2 * pi + 1][0] = r[1]; bf[2 * pi + 1][1] = r[3];
                    }
#pragma unroll
                    for (int ni = 0; ni < 4; ni++)
                        mma_f16(acc[ni], af, bf[ni]);
                }
                __syncthreads();
                buf ^= 1;
            }
#pragma unroll
            for (int ni = 0; ni < 4; ni++) {
                int r = m0 + wm + gid;
                int c = n0 + wn + ni * 8 + 2 * tig;
                float bv0 = bm1[c], bv1 = bm1[c + 1];
                g_dh[(size_t)r * MLPD + c]           = fmaxf(acc[ni][0] + bv0, 0.f);
                g_dh[(size_t)r * MLPD + c + 1]       = fmaxf(acc[ni][1] + bv1, 0.f);
                g_dh[(size_t)(r + 8) * MLPD + c]     = fmaxf(acc[ni][2] + bv0, 0.f);
                g_dh[(size_t)(r + 8) * MLPD + c + 1] = fmaxf(acc[ni][3] + bv1, 0.f);
            }
        }
        grid_bar(base + ++bc);
    }

    // ===== final: mlp2 of step-12 dh -> h_fin (192 CTAs x 4 rows) ===============
    if (bx < 192) {
        const int row0 = bx * 4;
        float* s_dh = (float*)smraw;
        const float4* src = (const float4*)(g_dh + (size_t)row0 * MLPD);
        float4* dst = (float4*)s_dh;
        for (int i = tid; i < 4 * MLPD / 4; i += 256) dst[i] = src[i];
        __syncthreads();
        int n = tid & 127, rg = tid >> 7;
        float bb = bm2[n];
        float a0 = bb, a1 = bb;
        const float* d0 = s_dh + (rg * 2 + 0) * MLPD;
        const float* d1 = s_dh + (rg * 2 + 1) * MLPD;
#pragma unroll 4
        for (int k2 = 0; k2 < MLPD / 2; k2++) {
            __half2 w = g_Wm2P[k2 * HDIM + n];
            float wl = __low2float(w), wh = __high2float(w);
            float2 x0 = *(const float2*)(d0 + 2 * k2);
            float2 x1 = *(const float2*)(d1 + 2 * k2);
            a0 += x0.x * wl; a0 += x0.y * wh;
            a1 += x1.x * wl; a1 += x1.y * wh;
        }
        float* ob = out + (size_t)TSTEPS * BATCH * 2;
        ob[(row0 + rg * 2 + 0) * HDIM + n] = fmaxf(a0, 0.f);
        ob[(row0 + rg * 2 + 1) * HDIM + n] = fmaxf(a1, 0.f);
    }
}

// ---------------- launch ----------------
extern "C" void kernel_launch(void* const* d_in, const int* in_sizes, int n_in,
                              void* d_out, int out_size) {
    const float* last_pos     = (const float*)d_in[0];
    const float* last_pos_rel = (const float*)d_in[1];
    const float* h0   = (const float*)d_in[2];
    const float* c0   = (const float*)d_in[3];
    /* d_in[4] = seq_start_end (uniform scenes; unused) */
    const float* W_se = (const float*)d_in[5];
    const float* b_se = (const float*)d_in[6];
    const float* W_ih = (const float*)d_in[7];
    const float* b_ih = (const float*)d_in[8];
    const float* W_hh = (const float*)d_in[9];
    const float* b_hh = (const float*)d_in[10];
    const float* W_hp = (const float*)d_in[11];
    const float* b_hp = (const float*)d_in[12];
    const float* W_pse = (const float*)d_in[13];
    const float* b_pse = (const float*)d_in[14];
    const float* W_p1 = (const float*)d_in[15];
    const float* b_p1 = (const float*)d_in[16];
    const float* W_p2 = (const float*)d_in[17];
    const float* b_p2 = (const float*)d_in[18];
    const float* W_m1 = (const float*)d_in[19];
    const float* b_m1 = (const float*)d_in[20];
    const float* W_m2 = (const float*)d_in[21];
    const float* b_m2 = (const float*)d_in[22];
    float* out = (float*)d_out;

    cudaFuncSetAttribute(decoder_persistent, cudaFuncAttributeMaxDynamicSharedMemorySize, SMEM_GP);

    setup_kernel<<<96, 256>>>(last_pos, last_pos_rel, h0, c0, W_se, b_se, W_pse, b_pse,
                              W_p1, b_p1, W_p2, W_m1, W_m2, W_ih, W_hh);
    decoder_persistent<<<NCTA, 256, SMEM_GP>>>(b_ih, b_hh, W_hp, b_hp, W_se, b_se,
                                               b_p2, b_m1, b_m2, out);
}